// round 17
// baseline (speedup 1.0000x reference)
#include <cuda_runtime.h>
#include <cuda_fp16.h>
#include <cstdint>
#include <math.h>

#define H_DIM 128
#define R_DIM 6
#define D_DIM 256
#define MAX_NODES 50000

// Scratch
__device__ __align__(128) float  g_agg[(size_t)MAX_NODES * H_DIM];   // 25.6 MB
// Pre-split weights (fp16 hi/lo): [0,32768) = W_up (256x128), then 3x Ws (256x256)
#define W_TOTAL (256*128 + 3*256*256)
__device__ __align__(128) __half g_whi[W_TOTAL];
__device__ __align__(128) __half g_wlo[W_TOTAL];

__device__ __forceinline__ uint32_t pack_h2(float a, float b) {
    __half2 v = __halves2half2(__float2half_rn(a), __float2half_rn(b));
    return *reinterpret_cast<uint32_t*>(&v);
}

// ---------------------------------------------------------------------------
// Prep kernels
// ---------------------------------------------------------------------------
__global__ void prep_w(const float* __restrict__ W_up, const float* __restrict__ Ws,
                       __half* __restrict__ whi, __half* __restrict__ wlo) {
    int i = blockIdx.x * blockDim.x + threadIdx.x;
    int stride = gridDim.x * blockDim.x;
    for (; i < W_TOTAL; i += stride) {
        float v = (i < 256 * 128) ? W_up[i] : Ws[i - 256 * 128];
        __half h = __float2half_rn(v);
        whi[i] = h;
        wlo[i] = __float2half_rn(v - __half2float(h));
    }
}

__global__ void zero2_kernel(float4* __restrict__ a, int n4a,
                             float4* __restrict__ o, int n4o) {
    int i = blockIdx.x * blockDim.x + threadIdx.x;
    int stride = gridDim.x * blockDim.x;
    float4 z = make_float4(0.f, 0.f, 0.f, 0.f);
    for (int k = i; k < n4a; k += stride) a[k] = z;
    for (int k = i; k < n4o; k += stride) o[k] = z;
}

// ---------------------------------------------------------------------------
// Edge stage (round-5 proven best: 2 edges/warp-iter, 4ch/lane, red.v4)
// ---------------------------------------------------------------------------
__global__ void edge_kernel(const float* __restrict__ x,
                            const float* __restrict__ rbf,
                            const int*   __restrict__ idx,
                            const float* __restrict__ Wrbf,
                            float*       __restrict__ agg,
                            int E) {
    const int lane = threadIdx.x & 31;
    const int warp = (blockIdx.x * blockDim.x + threadIdx.x) >> 5;
    const int nwarps = (gridDim.x * blockDim.x) >> 5;

    float w[4][6];
    #pragma unroll
    for (int j = 0; j < 4; ++j)
        #pragma unroll
        for (int r = 0; r < R_DIM; ++r)
            w[j][r] = __ldg(Wrbf + (lane * 4 + j) * R_DIM + r);

    for (int e0 = warp * 2; e0 < E; e0 += nwarps * 2) {
        const int e1 = e0 + 1;
        const bool has1 = e1 < E;

        const float2* rp0 = reinterpret_cast<const float2*>(rbf + (size_t)e0 * R_DIM);
        float2 a01 = __ldg(rp0 + 0), a23 = __ldg(rp0 + 1), a45 = __ldg(rp0 + 2);
        int n0 = __ldg(idx + e0);
        float4 xv0 = __ldg(reinterpret_cast<const float4*>(x + (size_t)e0 * H_DIM) + lane);

        float2 b01 = a01, b23 = a23, b45 = a45;
        int n1 = n0;
        float4 xv1 = make_float4(0.f, 0.f, 0.f, 0.f);
        if (has1) {
            const float2* rp1 = reinterpret_cast<const float2*>(rbf + (size_t)e1 * R_DIM);
            b01 = __ldg(rp1 + 0); b23 = __ldg(rp1 + 1); b45 = __ldg(rp1 + 2);
            n1 = __ldg(idx + e1);
            xv1 = __ldg(reinterpret_cast<const float4*>(x + (size_t)e1 * H_DIM) + lane);
        }

        #pragma unroll
        for (int pass = 0; pass < 2; ++pass) {
            float2 r01 = pass ? b01 : a01;
            float2 r23 = pass ? b23 : a23;
            float2 r45 = pass ? b45 : a45;
            float4 xv  = pass ? xv1 : xv0;
            int node   = pass ? n1 : n0;
            if (pass && !has1) break;

            float g0 = w[0][0]*r01.x + w[0][1]*r01.y + w[0][2]*r23.x + w[0][3]*r23.y + w[0][4]*r45.x + w[0][5]*r45.y;
            float g1 = w[1][0]*r01.x + w[1][1]*r01.y + w[1][2]*r23.x + w[1][3]*r23.y + w[1][4]*r45.x + w[1][5]*r45.y;
            float g2 = w[2][0]*r01.x + w[2][1]*r01.y + w[2][2]*r23.x + w[2][3]*r23.y + w[2][4]*r45.x + w[2][5]*r45.y;
            float g3 = w[3][0]*r01.x + w[3][1]*r01.y + w[3][2]*r23.x + w[3][3]*r23.y + w[3][4]*r45.x + w[3][5]*r45.y;

            float vx = g0 * xv.x, vy = g1 * xv.y, vz = g2 * xv.z, vw = g3 * xv.w;
            float* dst = agg + (size_t)node * H_DIM + lane * 4;
            asm volatile("red.global.add.v4.f32 [%0], {%1, %2, %3, %4};"
                         :: "l"(dst), "f"(vx), "f"(vy), "f"(vz), "f"(vw) : "memory");
        }
    }
}

// ---------------------------------------------------------------------------
// Fused MLP kernel: one 128-row tile per CTA through
//   up-proj (K=128) -> 3x silu layers (K=256) -> projection,
// activations resident in SMEM (double-buffered fp16 A), B streamed per
// (n-half, k-chunk). 256 threads, 8 warps of 32(m) x 64(n-within-half).
// ---------------------------------------------------------------------------
#define AST_HW   264                       // A row stride in halfwords (256 + 8)
#define ARR_A    (128 * AST_HW)            // 33792 hw per A buffer
#define BST_HW   72                        // B chunk row stride in halfwords
#define ARR_B_HW (128 * BST_HW)            // 9216 hw per B array
#define SM_A0    0
#define SM_A1    ARR_A
#define SM_BH    (2 * ARR_A)               // 67584
#define SM_BL    (2 * ARR_A + ARR_B_HW)    // 76800
#define SMEM_HW  (2 * ARR_A + 2 * ARR_B_HW)
#define SMEM_BYTES (SMEM_HW * 2)           // 172032 bytes

__device__ __forceinline__ void mma_f16(float* d, const uint32_t* a, uint32_t b0, uint32_t b1) {
    asm("mma.sync.aligned.m16n8k16.row.col.f32.f16.f16.f32 "
        "{%0,%1,%2,%3}, {%4,%5,%6,%7}, {%8,%9}, {%0,%1,%2,%3};"
        : "+f"(d[0]), "+f"(d[1]), "+f"(d[2]), "+f"(d[3])
        : "r"(a[0]), "r"(a[1]), "r"(a[2]), "r"(a[3]), "r"(b0), "r"(b1));
}

// One layer: reads fp16 A from sm[abase], writes fp16 y into sm[nbase] (or PROJ).
template<int KT, bool BIAS, bool SILU, bool PROJ>
__device__ __forceinline__ void do_layer(
    uint16_t* sm, int abase, int nbase,
    const __half* __restrict__ Bhi, const __half* __restrict__ Blo,
    const float* __restrict__ bias, const float* __restrict__ wout,
    float* __restrict__ out, int m0, int M)
{
    const int tid  = threadIdx.x;
    const int wid  = tid >> 5, lane = tid & 31;
    const int g    = lane >> 2, t = lane & 3;
    const int wm   = (wid & 3) * 32;
    const int wn   = (wid >> 2) * 64;

    const uint32_t* A32 = reinterpret_cast<const uint32_t*>(sm + abase);
    const uint32_t* B32h = reinterpret_cast<const uint32_t*>(sm + SM_BH);
    const uint32_t* B32l = reinterpret_cast<const uint32_t*>(sm + SM_BL);

    const int b_seg = tid & 7;     // uint4 segment within 64-col chunk
    const int b_rip = tid >> 3;    // row-in-pass (0..31)

    float s[4];
    if (PROJ) { s[0] = s[1] = s[2] = s[3] = 0.f; }

    #pragma unroll
    for (int nh = 0; nh < 2; ++nh) {
        float acc[2][8][4];
        #pragma unroll
        for (int i = 0; i < 2; ++i)
            #pragma unroll
            for (int j = 0; j < 8; ++j)
                #pragma unroll
                for (int q = 0; q < 4; ++q) acc[i][j][q] = 0.f;

        for (int c = 0; c < KT / 64; ++c) {
            // ---- fill B chunk: rows nh*128 .. +128, k-slice c*64..+64 ----
            #pragma unroll
            for (int p = 0; p < 4; ++p) {
                const int row = p * 32 + b_rip;
                const size_t off = (size_t)(nh * 128 + row) * KT + c * 64 + b_seg * 8;
                uint4 bh = *reinterpret_cast<const uint4*>(Bhi + off);
                uint4 bl = *reinterpret_cast<const uint4*>(Blo + off);
                const int hw = row * BST_HW + b_seg * 8;
                *reinterpret_cast<uint4*>(sm + SM_BH + hw) = bh;
                *reinterpret_cast<uint4*>(sm + SM_BL + hw) = bl;
            }
            __syncthreads();

            // ---- mma: 4 k16-steps x 2 products ----
            #pragma unroll
            for (int ks = 0; ks < 4; ++ks) {
                const int kofs = c * 32 + ks * 8;   // word offset into A row
                uint32_t ahi[2][4];
                #pragma unroll
                for (int i = 0; i < 2; ++i) {
                    int r0 = (wm + i * 16 + g) * (AST_HW / 2) + kofs + t;
                    ahi[i][0] = A32[r0];      ahi[i][1] = A32[r0 + 8 * (AST_HW / 2)];
                    ahi[i][2] = A32[r0 + 4];  ahi[i][3] = A32[r0 + 8 * (AST_HW / 2) + 4];
                }
                #pragma unroll
                for (int j = 0; j < 8; ++j) {
                    int nb = (wn + j * 8 + g) * (BST_HW / 2) + ks * 8 + t;
                    uint32_t bh0 = B32h[nb], bh1 = B32h[nb + 4];
                    uint32_t bl0 = B32l[nb], bl1 = B32l[nb + 4];
                    #pragma unroll
                    for (int i = 0; i < 2; ++i) {
                        mma_f16(acc[i][j], ahi[i], bh0, bh1);
                        mma_f16(acc[i][j], ahi[i], bl0, bl1);
                    }
                }
            }
            __syncthreads();
        }

        // ---- epilogue for this n-half ----
        #pragma unroll
        for (int i = 0; i < 2; ++i) {
            #pragma unroll
            for (int j = 0; j < 8; ++j) {
                const int col = nh * 128 + wn + j * 8 + t * 2;
                float b0 = BIAS ? __ldg(bias + col) : 0.f;
                float b1 = BIAS ? __ldg(bias + col + 1) : 0.f;
                float v0 = acc[i][j][0] + b0, v1 = acc[i][j][1] + b1;
                float v2 = acc[i][j][2] + b0, v3 = acc[i][j][3] + b1;
                if (SILU) {
                    v0 = v0 / (1.f + __expf(-v0)); v1 = v1 / (1.f + __expf(-v1));
                    v2 = v2 / (1.f + __expf(-v2)); v3 = v3 / (1.f + __expf(-v3));
                }
                if (PROJ) {
                    float w0 = __ldg(wout + col), w1 = __ldg(wout + col + 1);
                    s[i * 2 + 0] += v0 * w0 + v1 * w1;
                    s[i * 2 + 1] += v2 * w0 + v3 * w1;
                } else {
                    const int r0 = wm + i * 16 + g;
                    *reinterpret_cast<uint32_t*>(sm + nbase + r0 * AST_HW + col) = pack_h2(v0, v1);
                    *reinterpret_cast<uint32_t*>(sm + nbase + (r0 + 8) * AST_HW + col) = pack_h2(v2, v3);
                }
            }
        }
    }

    if (PROJ) {
        #pragma unroll
        for (int q = 0; q < 4; ++q) {
            s[q] += __shfl_xor_sync(0xffffffffu, s[q], 1);
            s[q] += __shfl_xor_sync(0xffffffffu, s[q], 2);
        }
        if (t == 0) {
            #pragma unroll
            for (int i = 0; i < 2; ++i) {
                int r0 = m0 + wm + i * 16 + g;
                if (r0 < M)
                    asm volatile("red.global.add.f32 [%0], %1;" :: "l"(out + r0), "f"(s[i*2]) : "memory");
                if (r0 + 8 < M)
                    asm volatile("red.global.add.f32 [%0], %1;" :: "l"(out + r0 + 8), "f"(s[i*2+1]) : "memory");
            }
        }
    }
}

__global__ void __launch_bounds__(256, 1)
fused_mlp(const float* __restrict__ agg,
          const __half* __restrict__ whi, const __half* __restrict__ wlo,
          const float* __restrict__ bs, const float* __restrict__ W_out,
          float* __restrict__ out, int M) {
    extern __shared__ __align__(16) uint16_t sm[];
    const int tid = threadIdx.x;
    const int m0  = blockIdx.x * 128;

    // ---- build A0 from agg (fp32 -> fp16), 128 rows x 128 cols ----
    {
        const int seg = tid & 31;      // col segment (4 floats)
        const int rp  = tid >> 5;      // row within pass (0..7)
        #pragma unroll
        for (int p = 0; p < 16; ++p) {
            const int row = p * 8 + rp;
            const int grow = m0 + row;
            float4 f = make_float4(0.f, 0.f, 0.f, 0.f);
            if (grow < M)
                f = *reinterpret_cast<const float4*>(agg + (size_t)grow * H_DIM + seg * 4);
            uint2 Hv;
            Hv.x = pack_h2(f.x, f.y);
            Hv.y = pack_h2(f.z, f.w);
            *reinterpret_cast<uint2*>(sm + SM_A0 + row * AST_HW + seg * 4) = Hv;
        }
    }
    // (first B-fill round's __syncthreads orders A0 build before first mma)

    const __half* whi_l = whi + 256 * 128;
    const __half* wlo_l = wlo + 256 * 128;

    // up-proj: A0 (K=128) -> A1
    do_layer<128, false, false, false>(sm, SM_A0, SM_A1, whi, wlo,
                                       nullptr, nullptr, nullptr, m0, M);
    // layer 0: A1 -> A0
    do_layer<256, true, true, false>(sm, SM_A1, SM_A0,
                                     whi_l + 0 * 65536, wlo_l + 0 * 65536,
                                     bs + 0 * D_DIM, nullptr, nullptr, m0, M);
    // layer 1: A0 -> A1
    do_layer<256, true, true, false>(sm, SM_A0, SM_A1,
                                     whi_l + 1 * 65536, wlo_l + 1 * 65536,
                                     bs + 1 * D_DIM, nullptr, nullptr, m0, M);
    // layer 2 + projection
    do_layer<256, true, true, true>(sm, SM_A1, SM_A0,
                                    whi_l + 2 * 65536, wlo_l + 2 * 65536,
                                    bs + 2 * D_DIM, W_out, out, m0, M);
}

// ---------------------------------------------------------------------------
// Launch
// Inputs: 0:x[E,128] 1:rbf[E,6] 2:i[E] 3:W_rbf[128,6] 4:W_up[256,128]
//         5:Ws[3,256,256] 6:bs[3,256] 7:W_out[1,256] (8:num_nodes)
// ---------------------------------------------------------------------------
extern "C" void kernel_launch(void* const* d_in, const int* in_sizes, int n_in,
                              void* d_out, int out_size) {
    const float* x     = (const float*)d_in[0];
    const float* rbf   = (const float*)d_in[1];
    const int*   idx   = (const int*)  d_in[2];
    const float* W_rbf = (const float*)d_in[3];
    const float* W_up  = (const float*)d_in[4];
    const float* Ws    = (const float*)d_in[5];
    const float* bs    = (const float*)d_in[6];
    const float* W_out = (const float*)d_in[7];
    float* out = (float*)d_out;

    const int E = in_sizes[2];
    const int M = out_size;

    float* agg;
    __half *whi, *wlo;
    cudaGetSymbolAddress((void**)&agg, g_agg);
    cudaGetSymbolAddress((void**)&whi, g_whi);
    cudaGetSymbolAddress((void**)&wlo, g_wlo);

    cudaFuncSetAttribute(fused_mlp, cudaFuncAttributeMaxDynamicSharedMemorySize, SMEM_BYTES);

    prep_w<<<224, 256>>>(W_up, Ws, whi, wlo);
    zero2_kernel<<<1024, 256>>>((float4*)agg, M * H_DIM / 4, (float4*)out, M / 4);

    edge_kernel<<<1184, 256>>>(x, rbf, idx, W_rbf, agg, E);

    const int tiles = (M + 127) / 128;
    fused_mlp<<<tiles, 256, SMEM_BYTES>>>(agg, whi, wlo, bs, W_out, out, M);
}